// round 7
// baseline (speedup 1.0000x reference)
#include <cuda_runtime.h>

constexpr int H = 256, W = 256, PLANES = 12;
constexpr int HH = 1024, WH = 1024;
constexpr float EPSF  = 1e-8f;
constexpr float EPSSF = 1e-12f;
constexpr int PSZ = PLANES * H * W;

constexpr int PRP = 49;   // halo pitch (48 + 1)
constexpr int HSP = 33;   // hsum pitch (32 + 1)

// hr_x prefetch bookkeeping: total float4 = 12*1024*1024/4 = 3,145,728.
// box1 streams the first half, box2 the second, 2048 f4 per block.
constexpr int PF_HALF = 1572864;

__device__ float  g_partial[768];
__device__ float  g_sink;
__device__ float2 g_ab [PSZ];    // interleaved (A, b)
__device__ float2 g_mab[PSZ];    // interleaved (meanA, meanb)

// ---------- K1: partial sums of |l_a|+eps ----------
__global__ void k_reduce1(const float* __restrict__ la) {
    __shared__ float sm[256];
    int t = threadIdx.x;
    float4 v = ((const float4*)la)[blockIdx.x * 256 + t];
    float s = fabsf(v.x) + fabsf(v.y) + fabsf(v.z) + fabsf(v.w) + 4.0f * EPSSF;
    sm[t] = s; __syncthreads();
    for (int off = 128; off > 0; off >>= 1) {
        if (t < off) sm[t] += sm[t + off];
        __syncthreads();
    }
    if (t == 0) g_partial[blockIdx.x] = sm[0];
}

__device__ __forceinline__ float pf_chunk(const float4* __restrict__ hr4,
                                          int base, int tp, int it0, int it1) {
    float s = 0.f;
    for (int it = it0; it < it1; it++) {
        float4 v = hr4[base + it * 64 + tp];
        s += v.x + v.y + v.z + v.w;
    }
    return s;
}

// ---------- K2: products + H-box + V-box + A,b; warps 8-9 prefetch hr ----------
constexpr int B1_AXY = 3 * 48 * PRP;            // 7056 floats
constexpr int B1_FL  = B1_AXY + 6 * 48 * HSP;   // 16560 floats (66240 B)

__device__ __forceinline__ void acc_prod(float* s, float a, float x, float y,
                                         float sign) {
    float ax  = a * x;
    float a2x = ax * a;
    s[0] += sign * a;
    s[1] += sign * a2x * y;
    s[2] += sign * a2x;
    s[3] += sign * a * y;
    s[4] += sign * ax * ax;
    s[5] += sign * ax;
}

__global__ __launch_bounds__(320)
void k_box1(const float* __restrict__ lx,
            const float* __restrict__ ly,
            const float* __restrict__ la,
            const float4* __restrict__ hr4) {
    extern __shared__ float smd[];
    float* sa = smd;
    float* sx = smd + 48 * PRP;
    float* sy = smd + 2 * 48 * PRP;
    float* hs = smd + B1_AXY;
    __shared__ float sred[256];
    __shared__ float s_inv;

    int t = threadIdx.x;
    bool comp = t < 256;
    int tp = t - 256;
    int pfbase = blockIdx.x * 2048;
    float pfs = 0.f;

    if (comp) sred[t] = g_partial[t] + g_partial[t + 256] + g_partial[t + 512];
    __syncthreads();
    for (int off = 128; off > 0; off >>= 1) {
        if (t < off) sred[t] += sred[t + off];
        __syncthreads();
    }
    if (t == 0) s_inv = 1.0f / sred[0];

    int plane = blockIdx.x >> 6, tile = blockIdx.x & 63;
    int R0 = (tile >> 3) * 32;
    int C0 = (tile & 7) * 32;
    int pbase = plane * H * W;

    if (comp) {
        // phase 1: stage 48x48 halo of a,x,y (zero outside image)
        for (int i = t; i < 48 * 48; i += 256) {
            int lr = i / 48, lc = i - lr * 48;
            int gr = R0 - 8 + lr, gc = C0 - 8 + lc;
            float a = 0.f, x = 0.f, y = 0.f;
            if (gr >= 0 && gr < H && gc >= 0 && gc < W) {
                int idx = pbase + gr * W + gc;
                a = fabsf(la[idx]) + EPSSF;
                x = lx[idx];
                y = ly[idx];
            }
            int o = lr * PRP + lc;
            sa[o] = a; sx[o] = x; sy[o] = y;
        }
    } else {
        pfs += pf_chunk(hr4, pfbase, tp, 0, 11);
    }
    __syncthreads();

    if (comp) {
        // phase 2: H-box with on-the-fly products
        for (int j = t; j < 384; j += 256) {
            int r = j >> 3, sg = j & 7;
            int base = r * PRP + sg * 4;
            float s[6] = {0,0,0,0,0,0};
#pragma unroll
            for (int k = 0; k < 17; k++)
                acc_prod(s, sa[base + k], sx[base + k], sy[base + k], 1.0f);
            int ho = r * HSP + sg * 4;
#pragma unroll
            for (int c = 0; c < 6; c++) hs[c * 48 * HSP + ho] = s[c];
#pragma unroll
            for (int i = 1; i < 4; i++) {
                int add = base + 16 + i, sub = base + i - 1;
                acc_prod(s, sa[add], sx[add], sy[add], 1.0f);
                acc_prod(s, sa[sub], sx[sub], sy[sub], -1.0f);
#pragma unroll
                for (int c = 0; c < 6; c++) hs[c * 48 * HSP + ho + i] = s[c];
            }
        }
    } else {
        pfs += pf_chunk(hr4, pfbase, tp, 11, 22);
    }
    __syncthreads();

    if (comp) {
        // phase 3: V-box + A,b
        float invS = s_inv;
        int col = t & 31, seg = t >> 5;
        int rl0 = seg * 4;
        float s[6] = {0,0,0,0,0,0};
#pragma unroll
        for (int k = 0; k < 17; k++) {
#pragma unroll
            for (int c = 0; c < 6; c++)
                s[c] += hs[(c * 48 + rl0 + k) * HSP + col];
        }
        int oc = C0 + col;
        int nx = min(W - 1, oc + 8) - max(0, oc - 8) + 1;

#pragma unroll
        for (int i = 0; i < 4; i++) {
            if (i > 0) {
#pragma unroll
                for (int c = 0; c < 6; c++)
                    s[c] += hs[(c * 48 + rl0 + 16 + i) * HSP + col]
                          - hs[(c * 48 + rl0 + i - 1) * HSP + col];
            }
            int orow = R0 + rl0 + i;
            int ny = min(H - 1, orow + 8) - max(0, orow - 8) + 1;
            float Nf = (float)(nx * ny);
            float invN = 1.0f / Nf;

            float m_a    = s[0] * invN;
            float m_a2xy = s[1] * invN;
            float m_tax  = invS * s[2] * invN;
            float m_ay   = s[3] * invN;
            float m_a2x2 = s[4] * invN;
            float m_ax   = s[5] * invN;

            float temp = fabsf(m_a2x2 - Nf * m_tax * m_ax);
            float A = (m_a2xy - Nf * m_tax * m_ay) / (temp + EPSF);
            float b = (m_ay - A * m_ax) / m_a;

            g_ab[pbase + orow * W + oc] = make_float2(A, b);
        }
    } else {
        pfs += pf_chunk(hr4, pfbase, tp, 22, 32);
        if (pfs == 1.2345e30f) g_sink = pfs;
    }
}

// ---------- K3: H-box + V-box of A,b -> means; warps 8-9 prefetch hr ----------
__global__ __launch_bounds__(320)
void k_box2(const float4* __restrict__ hr4) {
    __shared__ float ab [2 * 48 * PRP];
    __shared__ float hs2[2 * 48 * HSP];
    int t = threadIdx.x;
    bool comp = t < 256;
    int tp = t - 256;
    int pfbase = PF_HALF + blockIdx.x * 2048;
    float pfs = 0.f;

    int plane = blockIdx.x >> 6, tile = blockIdx.x & 63;
    int R0 = (tile >> 3) * 32;
    int C0 = (tile & 7) * 32;
    int pbase = plane * H * W;

    if (comp) {
        for (int i = t; i < 48 * 48; i += 256) {
            int lr = i / 48, lc = i - lr * 48;
            int gr = R0 - 8 + lr, gc = C0 - 8 + lc;
            float2 v = make_float2(0.f, 0.f);
            if (gr >= 0 && gr < H && gc >= 0 && gc < W)
                v = g_ab[pbase + gr * W + gc];
            ab[(0 * 48 + lr) * PRP + lc] = v.x;
            ab[(1 * 48 + lr) * PRP + lc] = v.y;
        }
    } else {
        pfs += pf_chunk(hr4, pfbase, tp, 0, 11);
    }
    __syncthreads();

    if (comp) {
        for (int j = t; j < 384; j += 256) {
            int r = j >> 3, sgc = j & 7;
            int lc0 = sgc * 4;
            float sav = 0.f, sbv = 0.f;
#pragma unroll
            for (int k = 0; k < 17; k++) {
                sav += ab[(0 * 48 + r) * PRP + lc0 + k];
                sbv += ab[(1 * 48 + r) * PRP + lc0 + k];
            }
            hs2[(0 * 48 + r) * HSP + lc0] = sav;
            hs2[(1 * 48 + r) * HSP + lc0] = sbv;
#pragma unroll
            for (int i = 1; i < 4; i++) {
                sav += ab[(0 * 48 + r) * PRP + lc0 + 16 + i]
                     - ab[(0 * 48 + r) * PRP + lc0 + i - 1];
                sbv += ab[(1 * 48 + r) * PRP + lc0 + 16 + i]
                     - ab[(1 * 48 + r) * PRP + lc0 + i - 1];
                hs2[(0 * 48 + r) * HSP + lc0 + i] = sav;
                hs2[(1 * 48 + r) * HSP + lc0 + i] = sbv;
            }
        }
    } else {
        pfs += pf_chunk(hr4, pfbase, tp, 11, 22);
    }
    __syncthreads();

    if (comp) {
        int col = t & 31, seg = t >> 5;
        int rl0 = seg * 4;
        float sav = 0.f, sbv = 0.f;
#pragma unroll
        for (int k = 0; k < 17; k++) {
            sav += hs2[(0 * 48 + rl0 + k) * HSP + col];
            sbv += hs2[(1 * 48 + rl0 + k) * HSP + col];
        }
        int oc = C0 + col;
        int nx = min(W - 1, oc + 8) - max(0, oc - 8) + 1;

#pragma unroll
        for (int i = 0; i < 4; i++) {
            if (i > 0) {
                sav += hs2[(0 * 48 + rl0 + 16 + i) * HSP + col]
                     - hs2[(0 * 48 + rl0 + i - 1) * HSP + col];
                sbv += hs2[(1 * 48 + rl0 + 16 + i) * HSP + col]
                     - hs2[(1 * 48 + rl0 + i - 1) * HSP + col];
            }
            int orow = R0 + rl0 + i;
            int ny = min(H - 1, orow + 8) - max(0, orow - 8) + 1;
            float invN = 1.0f / (float)(nx * ny);
            g_mab[pbase + orow * W + oc] = make_float2(sav * invN, sbv * invN);
        }
    } else {
        pfs += pf_chunk(hr4, pfbase, tp, 22, 32);
        if (pfs == 1.2345e30f) g_sink = pfs;
    }
}

// ---------- K4: bilinear 4x upsample fused with hr_x (MLP=4) ----------
__global__ __launch_bounds__(512)
void k_up(const float* __restrict__ hr, float* __restrict__ out) {
    __shared__ float2 sAB[8][257];
    int t = threadIdx.x;
    int plane = blockIdx.x >> 7;
    int g = blockIdx.x & 127;
    int Y0 = g * 8;
    int pb = plane * H * W;
    const float sc = 255.0f / 1023.0f;

#pragma unroll
    for (int jj = 0; jj < 4; jj++) {
        int j = t + jj * 512;
        int r = j >> 8, col = j & 255;
        float yf = (Y0 + r) * sc;
        int y0 = (int)yf;
        int y1 = min(y0 + 1, H - 1);
        float wy = yf - (float)y0;
        float2 v0 = g_mab[pb + y0 * W + col];
        float2 v1 = g_mab[pb + y1 * W + col];
        float2 res = make_float2(v0.x + (v1.x - v0.x) * wy,
                                 v0.y + (v1.y - v0.y) * wy);
        sAB[r][col] = res;
        if (col == 255) sAB[r][256] = res;
    }
    __syncthreads();

    int obase = plane * HH * WH + Y0 * WH;
    float4 h[4];
    int ho[4], x0s[4], rr[4], X0s[4];
#pragma unroll
    for (int jj = 0; jj < 4; jj++) {
        int i = t + jj * 512;
        int r = i >> 8, x4 = i & 255;
        int X0 = x4 * 4;
        rr[jj] = r; X0s[jj] = X0;
        ho[jj] = obase + r * WH + X0;
        h[jj] = *(const float4*)(hr + ho[jj]);
        x0s[jj] = (int)((float)X0 * sc);
    }
#pragma unroll
    for (int jj = 0; jj < 4; jj++) {
        float2 p0 = sAB[rr[jj]][x0s[jj]];
        float2 p1 = sAB[rr[jj]][x0s[jj] + 1];
        float2 p2 = sAB[rr[jj]][x0s[jj] + 2];
        float xv = (float)x0s[jj];
        float4 o;
        float* hv = (float*)&h[jj];
        float* ov = (float*)&o;
#pragma unroll
        for (int k = 0; k < 4; k++) {
            float xf = (float)(X0s[jj] + k) * sc;
            float d = xf - xv;
            bool st = d >= 1.0f;
            float wx = st ? d - 1.0f : d;
            float Av = st ? p1.x : p0.x;
            float Ah = st ? p2.x : p1.x;
            float Bv = st ? p1.y : p0.y;
            float Bh = st ? p2.y : p1.y;
            Av += (Ah - Av) * wx;
            Bv += (Bh - Bv) * wx;
            ov[k] = fmaf(Av, hv[k], Bv);
        }
        *(float4*)(out + ho[jj]) = o;
    }
}

extern "C" void kernel_launch(void* const* d_in, const int* in_sizes, int n_in,
                              void* d_out, int out_size) {
    const float* lr_x = (const float*)d_in[0];
    const float* lr_y = (const float*)d_in[1];
    const float* hr_x = (const float*)d_in[2];
    const float* l_a  = (const float*)d_in[3];
    float* out = (float*)d_out;
    const float4* hr4 = (const float4*)hr_x;

    static const int B1_SMEM = B1_FL * 4;    // 66240 B
    cudaFuncSetAttribute(k_box1, cudaFuncAttributeMaxDynamicSharedMemorySize,
                         B1_SMEM);

    k_reduce1<<<768, 256>>>(l_a);
    k_box1<<<PLANES * 64, 320, B1_SMEM>>>(lr_x, lr_y, l_a, hr4);
    k_box2<<<PLANES * 64, 320>>>(hr4);
    k_up<<<PLANES * 128, 512>>>(hr_x, out);
}